// round 14
// baseline (speedup 1.0000x reference)
#include <cuda_runtime.h>
#include <stdint.h>

// ---------------------------------------------------------------------------
// VanDerWallsSurface: scatter point features into a 128^3 voxel grid.
//  out[b,x,y,z] = [max f0, min f1, mean f2] over points whose sphere covers
//  the voxel (within the 5x5x5 neighborhood of round(coords)), else zeros.
//
// R13: R12's float4 sweep + warp-aligned scatter, with the Acc-zeroing race
// FIXED by phase separation.
//  R12 failure: threads zeroed Acc entries that other warps still had to
//  read (lines span warp/iteration boundaries) -> stale mix {cnt!=0,maxk=0}
//  -> funkey(0) = NaN.
//  R13 sweep: phase 1 reads Acc + stores output float4s (no Acc writes);
//  __syncthreads(); phase 2 zeroes dirty lines (1 thread/line, block owns
//  exactly 256 lines so the barrier fully orders reads before zeroes).
//
//  - Order-preserving uint encodings make 0 the neutral element for all four
//    accumulators -> scratch is a zero-initialized static; the sweep re-zeroes
//    dirty Acc lines and its bitmap words: all-zero across graph replays.
// ---------------------------------------------------------------------------

#define VOL        128
#define NB         4
#define NPTS       4096
#define NPOINTS    (NB * NPTS)            // 16384
#define TOTAL_VOX  (NB * VOL * VOL * VOL) // 8,388,608
#define NLINES     (TOTAL_VOX / 8)        // 1,048,576 (8 Acc per 128B line)
#define NWORDS     (NLINES / 32)          // 32,768 bitmap words
#define TPB        256

#define SCAT_BLOCKS  (NPOINTS * 128 / TPB)   // 8,192 (128 threads/point)

#define OUT4_TOTAL   (TOTAL_VOX * 3 / 4)     // 6,291,456 output float4
#define F4_PER_BLK   1536                    // = 256 lines = 8 bitmap words
#define SWEEP_ITERS  (F4_PER_BLK / TPB)      // 6
#define SWEEP_BLOCKS (OUT4_TOTAL / F4_PER_BLK) // 4,096
#define WPB          8                       // bitmap words per sweep block

// Interleaved per-voxel accumulator: one 128B cache line covers all four
// fields of 8 z-adjacent voxels. All neutral elements are 0.
struct Acc {
    unsigned int maxk;  // max-key of f0
    unsigned int mink;  // ~min-key of f1 (min via max)
    unsigned int cnt;   // hit count
    float        sum;   // sum of f2
};
__device__ Acc          g_acc[TOTAL_VOX];  // zero-init; kept zero by k_sweep
__device__ unsigned int g_dirty[NWORDS];   // 1 bit per Acc line; cleared by k_sweep

// Order-preserving float -> uint key. For any finite non-NaN f, fkey(f) > 0,
// so 0 is a valid "empty" sentinel for atomicMax accumulation.
__device__ __forceinline__ unsigned int fkey(float f) {
    unsigned int u = __float_as_uint(f);
    return (u & 0x80000000u) ? ~u : (u | 0x80000000u);
}
__device__ __forceinline__ float funkey(unsigned int k) {
    unsigned int u = (k & 0x80000000u) ? (k ^ 0x80000000u) : ~k;
    return __uint_as_float(u);
}

// Decode one Acc (as uint4) into its 3 output channels.
__device__ __forceinline__ void decode(uint4 a, float* v) {
    v[0] = 0.0f; v[1] = 0.0f; v[2] = 0.0f;
    if (a.z != 0u) {
        v[0] = funkey(a.x);
        v[1] = funkey(~a.y);
        v[2] = __fdiv_rn(__uint_as_float(a.w), (float)a.z);
    }
}

// Kernel A: 128 threads per point (warp-uniform point), lanes k<125 are the
// 5x5x5 offsets; hits do 4 atomics into the voxel's interleaved Acc plus one
// dirty-bit atomicOr per touched line.
__global__ void __launch_bounds__(TPB) k_scatter(
    const float4* __restrict__ cr,     // (B*N) x [cx, cy, cz, r]
    const float*  __restrict__ feat)   // (B*N) x 3
{
    int t  = blockIdx.x * TPB + threadIdx.x;
    int pn = t >> 7;                    // point id (warp-uniform)
    int k  = t & 127;                   // offset id
    if (k >= 125) return;

    float4 c = __ldg(cr + pn);          // warp-uniform -> single broadcast

    int ox = k / 25 - 2;
    int oy = (k / 5) % 5 - 2;
    int oz = k % 5 - 2;

    // jnp.round == round-half-to-even == rn conversions
    int vx = __float2int_rn(c.x) + ox;
    int vy = __float2int_rn(c.y) + oy;
    int vz = __float2int_rn(c.z) + oz;

    // Exact IEEE ops, left-to-right sum, matching the reference (no FMA
    // contraction that could flip sphere-boundary membership).
    float dx = __fsub_rn((float)vx, c.x);
    float dy = __fsub_rn((float)vy, c.y);
    float dz = __fsub_rn((float)vz, c.z);
    float d2 = __fadd_rn(__fadd_rn(__fmul_rn(dx, dx), __fmul_rn(dy, dy)),
                         __fmul_rn(dz, dz));

    float rr = __fdiv_rn(rintf(__fmul_rn(c.w, 1000.0f)), 1000.0f);
    float r2 = __fmul_rn(rr, rr);

    bool ok = (d2 <= r2)
            && ((unsigned)vx < VOL) && ((unsigned)vy < VOL) && ((unsigned)vz < VOL);
    if (!ok) return;

    unsigned e = (unsigned)((pn >> 12) * (VOL * VOL * VOL)
                            + ((vx * VOL + vy) * VOL + vz));

    const float* fp = feat + (size_t)pn * 3;
    float f0 = __ldg(fp + 0);
    float f1 = __ldg(fp + 1);
    float f2 = __ldg(fp + 2);

    Acc* a = &g_acc[e];
    atomicMax(&a->maxk, fkey(f0));
    atomicMax(&a->mink, ~fkey(f1));     // min via max of complemented key
    atomicAdd(&a->cnt, 1u);
    atomicAdd(&a->sum, f2);

    unsigned line = e >> 3;             // 8 Acc per 128B line
    atomicOr(&g_dirty[line >> 5], 1u << (line & 31u));
}

// Kernel B: one thread per output float4, two phases.
// Block b owns float4 [b*1536, +1536) = lines [b*256, +256) = bitmap words
// [b*8, +8) (cached in smem).
// Phase 1 (reads only): clean line -> STG.128 zeros; dirty -> read the 2 Acc
// entries the float4 spans, decode, select by i%3, store.
// Phase 2 (after barrier): one thread per line zeroes its dirty line; then
// threads 0..7 clear the bitmap words. No thread zeroes what another reads.
__global__ void __launch_bounds__(TPB) k_sweep(float4* __restrict__ out4)
{
    __shared__ unsigned s_w[WPB];

    unsigned b = blockIdx.x;
    if (threadIdx.x < WPB) s_w[threadIdx.x] = g_dirty[b * WPB + threadIdx.x];
    __syncthreads();

    // ---- Phase 1: decode + output stores (no Acc writes) ----
#pragma unroll
    for (int it = 0; it < SWEEP_ITERS; it++) {
        unsigned il = it * TPB + threadIdx.x;        // local float4 in [0,1536)
        unsigned Ll = il / 6;                        // local line in [0,256)
        unsigned w  = s_w[Ll >> 5];
        unsigned i  = b * F4_PER_BLK + il;           // global float4 index

        if (((w >> (Ll & 31u)) & 1u) == 0u) {        // clean line (common)
            out4[i] = make_float4(0.f, 0.f, 0.f, 0.f);
        } else {
            unsigned m  = il % 3;                    // == i%3 (b*1536 ≡ 0 mod 3)
            unsigned v0 = (4u * i) / 3u;             // first voxel spanned
            const uint4* ap0 = reinterpret_cast<const uint4*>(g_acc) + v0;
            uint4 a0 = ap0[0];
            uint4 a1 = ap0[1];                       // stays within the line

            float A[3], B[3];
            decode(a0, A);
            decode(a1, B);

            float4 v;
            if (m == 0)      v = make_float4(A[0], A[1], A[2], B[0]);
            else if (m == 1) v = make_float4(A[1], A[2], B[0], B[1]);
            else             v = make_float4(A[2], B[0], B[1], B[2]);
            out4[i] = v;
        }
    }

    // ---- Phase 2: zero dirty Acc lines (all reads completed above) ----
    __syncthreads();
    {
        unsigned w = s_w[threadIdx.x >> 5];          // line = threadIdx.x
        if ((w >> (threadIdx.x & 31u)) & 1u) {
            uint4* lp = reinterpret_cast<uint4*>(g_acc)
                      + ((size_t)b * 256 + threadIdx.x) * 8;
            uint4 z = make_uint4(0u, 0u, 0u, 0u);
#pragma unroll
            for (int j = 0; j < 8; j++) lp[j] = z;   // self-clean for next call
        }
    }
    if (threadIdx.x < WPB && s_w[threadIdx.x] != 0u)
        g_dirty[b * WPB + threadIdx.x] = 0u;
}

extern "C" void kernel_launch(void* const* d_in, const int* in_sizes, int n_in,
                              void* d_out, int out_size)
{
    const float4* cr   = (const float4*)d_in[0];  // coordinates_radii (B,N,4)
    const float*  feat = (const float*)d_in[1];   // features (B,N,3)
    float4*       out4 = (float4*)d_out;          // (B,128,128,128,3) f32

    k_scatter<<<SCAT_BLOCKS, TPB>>>(cr, feat);
    k_sweep<<<SWEEP_BLOCKS, TPB>>>(out4);
}